// round 17
// baseline (speedup 1.0000x reference)
#include <cuda_runtime.h>

// ---------------- Problem constants (fixed by setup_inputs) ----------------
namespace {
constexpr int B = 8;
constexpr int S = 2048;
constexpr int D = 2048;
constexpr int M = 4088;          // merged length
constexpr int TOK_IN  = 128011;
constexpr int TOK_OUT = 128012;
constexpr int TOK_PAD = 128001;
constexpr int IGNORE_ID = -100;
constexpr int MAX_PH_ROW = 128;  // max placeholders per row (actual: 8)
}

// ---------------- Device scratch (no dynamic allocation allowed) -----------
// Per-batch placeholder interval table (sorted by position):
//   x = cstart, y = cend (inclusive), z = (kind<<28)|st,
//   w = extra_through = cend - shift - s
__device__ int4 g_ph[B][MAX_PH_ROW];
__device__ int  g_hdr[2 * B];      // [2b] = shift, [2b+1] = nph

// ---------------- Block-wide exclusive scan, 256 threads (8 warps) ---------
__device__ __forceinline__ int blk_excl_scan(int v, int& total, int* s_warp) {
    const unsigned FULL = 0xFFFFFFFFu;
    int lane = threadIdx.x & 31, wid = threadIdx.x >> 5;
    int x = v;
#pragma unroll
    for (int o = 1; o < 32; o <<= 1) {
        int y = __shfl_up_sync(FULL, x, o);
        if (lane >= o) x += y;
    }
    if (lane == 31) s_warp[wid] = x;
    __syncthreads();
    if (wid == 0 && lane < 8) {
        int t = s_warp[lane];
        int xt = t;
#pragma unroll
        for (int o = 1; o < 8; o <<= 1) {
            int y = __shfl_up_sync(0xFFu, xt, o);
            if (lane >= o) xt += y;
        }
        s_warp[lane] = xt - t;
        if (lane == 7) s_warp[8] = xt;
    }
    __syncthreads();
    total = s_warp[8];
    int res = s_warp[wid] + x - v;
    __syncthreads();
    return res;
}

__device__ __forceinline__ void count_rows(const int* __restrict__ ids,
                                           int* s_cin, int* s_cout) {
    int w = threadIdx.x >> 5, lane = threadIdx.x & 31;
    int cin = 0, cout = 0;
    for (int s = lane; s < S; s += 32) {
        int v = ids[w * S + s];
        cin  += (v == TOK_IN);
        cout += (v == TOK_OUT);
    }
#pragma unroll
    for (int o = 16; o; o >>= 1) {
        cin  += __shfl_down_sync(0xFFFFFFFFu, cin, o);
        cout += __shfl_down_sync(0xFFFFFFFFu, cout, o);
    }
    if (lane == 0) { s_cin[w] = cin; s_cout[w] = cout; }
}

// ---------------- Kernel A: placeholder interval table (critical path) ------
__global__ void __launch_bounds__(256) k_plan(
        const int* __restrict__ ids,
        const int* __restrict__ in_starts,
        const int* __restrict__ out_starts,
        int n_in, int n_out, int tot_in, int tot_out) {
    __shared__ int s_ids[S];
    __shared__ int s_warp[9];
    __shared__ int s_cin[B], s_cout[B];
    const int b = blockIdx.x, t = threadIdx.x;

    count_rows(ids, s_cin, s_cout);
    for (int s = t; s < S; s += 256) s_ids[s] = ids[b * S + s];
    __syncthreads();

    int ib = 0, ob = 0;
    for (int r = 0; r < b; r++) { ib += s_cin[r]; ob += s_cout[r]; }
    const int row_in = s_cin[b], row_out = s_cout[b];

    const int base = t * 8;
    int vin[8], vout[8], tpn[8], stv[8];
    int lin = 0, lout = 0;
#pragma unroll
    for (int j = 0; j < 8; j++) {
        int v = s_ids[base + j];
        vin[j]  = (v == TOK_IN);
        vout[j] = (v == TOK_OUT);
        lin += vin[j]; lout += vout[j];
    }
    int dummy;
    int ex = blk_excl_scan((lin << 16) | lout, dummy, s_warp);
    const int ex_in = ex >> 16, ex_out = ex & 0xFFFF;

    {
        int oin = ex_in, oout = ex_out;
#pragma unroll
        for (int j = 0; j < 8; j++) {
            int v = 1, st = 0;
            if (vin[j]) {
                int p = ib + oin; oin++;
                st = in_starts[p];
                v = ((p + 1 < n_in) ? in_starts[p + 1] : tot_in) - st;
            } else if (vout[j]) {
                int p = ob + oout; oout++;
                st = out_starts[p];
                v = ((p + 1 < n_out) ? out_starts[p + 1] : tot_out) - st;
            }
            tpn[j] = v; stv[j] = st;
        }
    }
    int tsum = 0;
#pragma unroll
    for (int j = 0; j < 8; j++) tsum += tpn[j];
    int total;
    int ex2 = blk_excl_scan(tsum, total, s_warp);
    const int shift = M - total;

    {
        int run = ex2;
        int comb = ex_in + ex_out;       // combined placeholder ordinal base
#pragma unroll
        for (int j = 0; j < 8; j++) {
            run += tpn[j];
            if (vin[j] || vout[j]) {
                const int np = run - 1 + shift;        // cend
                const int cstart = np - tpn[j] + 1;
                const int s = base + j;
                const int kind = vin[j] ? 1 : 2;
                g_ph[b][comb] = make_int4(cstart, np,
                                          (kind << 28) | stv[j],
                                          np - shift - s);
                comb++;
            }
        }
    }
    if (t == 0) {
        g_hdr[2 * b]     = shift;
        g_hdr[2 * b + 1] = row_in + row_out;
    }
    __syncthreads();
#if __CUDA_ARCH__ >= 900
    cudaTriggerProgrammaticLaunchCompletion();
#endif
}

// ---------------- source resolution from the interval table -----------------
__device__ __forceinline__ const float4* resolve(
        int bY, int m, int shift, int nph,
        const float* in_emb, const float* out_emb, const float* text_emb) {
    if (m < shift) return nullptr;
    int kind = 0, idx = 0, extra = 0;
    bool audio = false;
    for (int p = 0; p < nph; p++) {
        const int4 e = g_ph[bY][p];
        if (m >= e.x) {
            if (m <= e.y) {
                kind = e.z >> 28;
                idx  = (e.z & 0x0FFFFFFF) + (m - e.x);
                audio = true;
                break;
            }
            extra = e.w;
        } else break;
    }
    if (!audio) { kind = 0; idx = m - shift - extra; }
    const float* sp;
    if (kind == 0)      sp = text_emb + ((long long)bY * S + idx) * D;
    else if (kind == 1) sp = in_emb  + (long long)idx * D;
    else                sp = out_emb + (long long)idx * D;
    return reinterpret_cast<const float4*>(sp);
}

// ---------------- Kernel C: 2 rows per 256-thread block, MLP=4/thread -------
// Grid (M/2, B). Thread t moves row0[t], row0[t+256], row1[t], row1[t+256]
// — 4 independent float4 in flight, half the CTA count of the 1-row config.
__global__ void __launch_bounds__(256) k_copy(const float* __restrict__ in_emb,
                                              const float* __restrict__ out_emb,
                                              const float* __restrict__ text_emb,
                                              float* __restrict__ out) {
#if __CUDA_ARCH__ >= 900
    cudaGridDependencySynchronize();
#endif
    const int bY = blockIdx.y;                       // batch
    const int m0 = blockIdx.x * 2;                   // first merged column
    const int t  = threadIdx.x;

    const int shift = __ldg(&g_hdr[2 * bY]);
    const int nph   = __ldg(&g_hdr[2 * bY + 1]);

    const float4* a0 = resolve(bY, m0,     shift, nph, in_emb, out_emb, text_emb);
    const float4* a1 = resolve(bY, m0 + 1, shift, nph, in_emb, out_emb, text_emb);

    const float4 z = make_float4(0.f, 0.f, 0.f, 0.f);
    float4 v0, v1, w0, w1;
    // 4 independent streaming loads, front-batched
    if (a0) { v0 = __ldcs(a0 + t); v1 = __ldcs(a0 + t + 256); }
    else    { v0 = z; v1 = z; }
    if (a1) { w0 = __ldcs(a1 + t); w1 = __ldcs(a1 + t + 256); }
    else    { w0 = z; w1 = z; }

    float4* d0 = reinterpret_cast<float4*>(out)
               + ((long long)bY * M + m0) * (D / 4) + t;
    __stcs(d0,       v0);
    __stcs(d0 + 256, v1);
    float4* d1 = d0 + (D / 4);
    __stcs(d1,       w0);
    __stcs(d1 + 256, w1);
}

// ---------------- Kernel B: all small float outputs (side stream) -----------
__global__ void __launch_bounds__(256) k_small(
        const int* __restrict__ ids,
        const int* __restrict__ amask,
        const int* __restrict__ labels,
        const int* __restrict__ in_starts,
        const int* __restrict__ out_starts,
        int n_in, int n_out, int tot_in, int tot_out,
        float* __restrict__ out) {
    __shared__ int s_ids[S];
    __shared__ int s_attn[M];
    __shared__ int s_warp[9];
    __shared__ int s_cin[B], s_cout[B];
    __shared__ int s_ph_np[MAX_PH_ROW], s_ph_st[MAX_PH_ROW],
                   s_ph_len[MAX_PH_ROW], s_ph_kind[MAX_PH_ROW];
    const int b = blockIdx.x, t = threadIdx.x;

    float* o_attn = out + (long long)B * M * D;
    float* o_lab  = o_attn + (long long)B * M;
    float* o_pos  = o_lab  + (long long)B * M;
    float* o_id   = o_pos  + (long long)B * M;
    float* o_ifil = o_id   + (long long)B * M;
    float* o_idis = o_ifil + (long long)B * M;
    float* o_ofil = o_idis + (long long)B * M;

    count_rows(ids, s_cin, s_cout);
    for (int s = t; s < S; s += 256) s_ids[s] = ids[b * S + s];
    for (int m = t; m < M; m += 256) s_attn[m] = 0;
    for (int m = t; m < M; m += 256) {
        int idx = b * M + m;
        o_lab[idx]  = (float)IGNORE_ID;
        o_id[idx]   = (float)TOK_PAD;
        o_ifil[idx] = 0.0f;
        o_idis[idx] = 0.0f;
        o_ofil[idx] = 0.0f;
    }
    __syncthreads();

    int ib = 0, ob = 0;
    for (int r = 0; r < b; r++) { ib += s_cin[r]; ob += s_cout[r]; }
    const int row_in = s_cin[b];

    const int base = t * 8;
    int vin[8], vout[8], tpn[8];
    int lin = 0, lout = 0;
#pragma unroll
    for (int j = 0; j < 8; j++) {
        int v = s_ids[base + j];
        vin[j]  = (v == TOK_IN);
        vout[j] = (v == TOK_OUT);
        lin += vin[j]; lout += vout[j];
    }
    int dummy;
    int ex = blk_excl_scan((lin << 16) | lout, dummy, s_warp);
    const int ex_in = ex >> 16, ex_out = ex & 0xFFFF;

    {
        int oin = ex_in, oout = ex_out;
#pragma unroll
        for (int j = 0; j < 8; j++) {
            int v = 1;
            if (vin[j]) {
                int p = ib + oin; oin++;
                int st = in_starts[p];
                v = ((p + 1 < n_in) ? in_starts[p + 1] : tot_in) - st;
            } else if (vout[j]) {
                int p = ob + oout; oout++;
                int st = out_starts[p];
                v = ((p + 1 < n_out) ? out_starts[p + 1] : tot_out) - st;
            }
            tpn[j] = v;
        }
    }
    int tsum = 0;
#pragma unroll
    for (int j = 0; j < 8; j++) tsum += tpn[j];
    int total;
    int ex2 = blk_excl_scan(tsum, total, s_warp);
    const int shift = M - total;

    {
        int run = ex2, oin = ex_in, oout = ex_out;
#pragma unroll
        for (int j = 0; j < 8; j++) {
            run += tpn[j];
            const int np = run - 1 + shift;
            const int s  = base + j;
            if (vin[j]) {
                int lp = oin; oin++;
                s_ph_np[lp] = np; s_ph_st[lp] = in_starts[ib + lp];
                s_ph_len[lp] = tpn[j]; s_ph_kind[lp] = 1;
            } else if (vout[j]) {
                int lp = row_in + oout; oout++;
                s_ph_np[lp] = np; s_ph_st[lp] = out_starts[ob + (lp - row_in)];
                s_ph_len[lp] = tpn[j]; s_ph_kind[lp] = 2;
            } else {
                int idx = b * M + np;
                s_attn[np] = amask[b * S + s];
                o_lab[idx] = (float)labels[b * S + s];
                o_id[idx]  = (float)s_ids[s];
            }
        }
    }
    __syncthreads();

    const int nph = row_in + s_cout[b];
    for (int ph = 0; ph < nph; ph++) {
        const int np = s_ph_np[ph];
        const int len = s_ph_len[ph], kind = s_ph_kind[ph];
        const int cstart = np - len + 1;
        for (int j = t; j < len; j += 256) {
            int c   = cstart + j;
            int idx = b * M + c;
            s_attn[c]  = 1;
            o_lab[idx] = (float)IGNORE_ID;
            o_id[idx]  = (float)(kind == 1 ? TOK_IN : TOK_OUT);
            if (kind == 1) { o_ifil[idx] = 1.0f; o_idis[idx] = 1.0f; }
            else           { o_ofil[idx] = 1.0f; }
        }
    }
    __syncthreads();

    int a[16];
    int sum = 0;
#pragma unroll
    for (int j = 0; j < 16; j++) {
        int m = t * 16 + j;
        a[j] = (m < M) ? s_attn[m] : 0;
        sum += a[j];
    }
    int tot2;
    int ex3 = blk_excl_scan(sum, tot2, s_warp);
    int run = ex3;
#pragma unroll
    for (int j = 0; j < 16; j++) {
        run += a[j];
        int m = t * 16 + j;
        if (m < M) {
            int idx = b * M + m;
            o_attn[idx] = (float)a[j];
            o_pos[idx]  = (float)((a[j] == 0) ? 1 : (run - 1));
        }
    }
}

// ---------------- Launch -----------------------------------------------------
extern "C" void kernel_launch(void* const* d_in, const int* in_sizes, int n_in_args,
                              void* d_out, int out_size) {
    const float* audio_in_embed  = (const float*)d_in[0];
    const float* audio_out_embed = (const float*)d_in[1];
    const float* inputs_embeds   = (const float*)d_in[2];
    const int*   in_starts       = (const int*)d_in[3];
    const int*   out_starts      = (const int*)d_in[4];
    const int*   input_ids       = (const int*)d_in[5];
    const int*   attention_mask  = (const int*)d_in[6];
    const int*   label_ids       = (const int*)d_in[7];
    (void)n_in_args; (void)out_size;

    const int n_in  = in_sizes[3];
    const int n_out = in_sizes[4];
    const int tot_in  = in_sizes[0] / D;
    const int tot_out = in_sizes[1] / D;

    float* out = (float*)d_out;
    const dim3 copy_grid(M / 2, B);

    // Fork-join: k_small on a side stream overlaps the critical path
    // (k_plan -> k_copy). Disjoint output regions.
    cudaStream_t side = nullptr;
    cudaEvent_t e_fork = nullptr, e_join = nullptr;
    bool forked =
        (cudaStreamCreateWithFlags(&side, cudaStreamNonBlocking) == cudaSuccess) &&
        (cudaEventCreateWithFlags(&e_fork, cudaEventDisableTiming) == cudaSuccess) &&
        (cudaEventCreateWithFlags(&e_join, cudaEventDisableTiming) == cudaSuccess);
    forked = forked && (cudaEventRecord(e_fork, 0) == cudaSuccess) &&
             (cudaStreamWaitEvent(side, e_fork, 0) == cudaSuccess);

    if (forked)
        k_small<<<B, 256, 0, side>>>(input_ids, attention_mask, label_ids,
                                     in_starts, out_starts,
                                     n_in, n_out, tot_in, tot_out, out);
    else
        k_small<<<B, 256>>>(input_ids, attention_mask, label_ids,
                            in_starts, out_starts,
                            n_in, n_out, tot_in, tot_out, out);

    k_plan<<<B, 256>>>(input_ids, in_starts, out_starts,
                       n_in, n_out, tot_in, tot_out);

    // k_copy with PDL attempt (inert at worst; fallback is plain launch).
    {
        cudaLaunchConfig_t cfg = {};
        cfg.gridDim  = copy_grid;
        cfg.blockDim = dim3(256, 1, 1);
        cfg.dynamicSmemBytes = 0;
        cfg.stream   = 0;
        cudaLaunchAttribute attr[1];
        attr[0].id = cudaLaunchAttributeProgrammaticStreamSerialization;
        attr[0].val.programmaticStreamSerializationAllowed = 1;
        cfg.attrs    = attr;
        cfg.numAttrs = 1;
        cudaError_t e = cudaLaunchKernelEx(&cfg, k_copy,
                                           audio_in_embed, audio_out_embed,
                                           inputs_embeds, out);
        if (e != cudaSuccess) {
            k_copy<<<copy_grid, 256>>>(audio_in_embed, audio_out_embed,
                                       inputs_embeds, out);
        }
    }

    if (forked) {
        cudaEventRecord(e_join, side);
        cudaStreamWaitEvent(0, e_join, 0);
    }
}